// round 1
// baseline (speedup 1.0000x reference)
#include <cuda_runtime.h>
#include <math.h>

#define NPTS 16384
#define CD   512
#define DIN  1024
#define DST  16
#define DBCW 64       // DT_RANK(32) + 2*D_STATE(32)
#define MLPD 1024
#define NCH  128      // chunks
#define TCH  128      // steps per chunk (NCH*TCH == NPTS)

// ---------------- scratch (device globals; no allocation allowed) ----------------
__device__ __align__(16) float g_f  [NPTS*CD];
__device__ __align__(16) float g_u  [NPTS*CD];       // ln1 out, later reused for x2
__device__ __align__(16) float g_xz [NPTS*2*DIN];
__device__ __align__(16) float g_xc [NPTS*DIN];
__device__ __align__(16) float g_dbc[NPTS*DBCW];
__device__ __align__(16) float g_dt [NPTS*DIN];
__device__ __align__(16) float g_y  [NPTS*DIN];
__device__ __align__(16) float g_x1 [NPTS*CD];
__device__ __align__(16) float g_h2 [NPTS*CD];
__device__ __align__(16) float g_g  [NPTS*MLPD];
__device__ __align__(16) float g_An [DIN*DST];
__device__ __align__(16) float g_Hc [NCH*DIN*DST];
__device__ __align__(16) float g_sd [NCH*DIN];
__device__ __align__(16) float g_hi [NCH*DIN*DST];

// ---------------- generic fp32 GEMM: C = A @ op(B) (+bias)(+add) ----------------
// BT=true : B is (Nn,K) row-major, compute A@B^T.   BT=false: B is (K,Nn) row-major.
template<bool BT>
__global__ __launch_bounds__(256) void sgemm(
    const float* __restrict__ A, int lda,
    const float* __restrict__ B, int ldb,
    const float* __restrict__ bias,
    const float* __restrict__ add,
    float* __restrict__ Cc, int ldc,
    int M, int Nn, int K)
{
    __shared__ float As[8][128];
    __shared__ float Bs[8][128];
    const int tid = threadIdx.x;
    const int tx = tid & 15, ty = tid >> 4;
    const int m0 = blockIdx.y * 128, n0 = blockIdx.x * 128;

    float acc[8][8];
#pragma unroll
    for (int i = 0; i < 8; i++)
#pragma unroll
        for (int j = 0; j < 8; j++) acc[i][j] = 0.f;

    const int arow = tid >> 1, akk = (tid & 1) * 4;

    for (int k0 = 0; k0 < K; k0 += 8) {
        float4 av = *(const float4*)(A + (size_t)(m0 + arow) * lda + k0 + akk);
        As[akk+0][arow] = av.x; As[akk+1][arow] = av.y;
        As[akk+2][arow] = av.z; As[akk+3][arow] = av.w;
        if (BT) {
            float4 bv = make_float4(0.f, 0.f, 0.f, 0.f);
            if (n0 + arow < Nn)
                bv = *(const float4*)(B + (size_t)(n0 + arow) * ldb + k0 + akk);
            Bs[akk+0][arow] = bv.x; Bs[akk+1][arow] = bv.y;
            Bs[akk+2][arow] = bv.z; Bs[akk+3][arow] = bv.w;
        } else {
            int bk = tid >> 5, bn = (tid & 31) * 4;
            float4 bv = make_float4(0.f, 0.f, 0.f, 0.f);
            if (n0 + bn < Nn)
                bv = *(const float4*)(B + (size_t)(k0 + bk) * ldb + n0 + bn);
            *(float4*)(&Bs[bk][bn]) = bv;
        }
        __syncthreads();
#pragma unroll
        for (int kk = 0; kk < 8; kk++) {
            float a[8], b[8];
            float4 a0 = *(const float4*)(&As[kk][ty * 4]);
            float4 a1 = *(const float4*)(&As[kk][ty * 4 + 64]);
            float4 b0 = *(const float4*)(&Bs[kk][tx * 4]);
            float4 b1 = *(const float4*)(&Bs[kk][tx * 4 + 64]);
            a[0]=a0.x; a[1]=a0.y; a[2]=a0.z; a[3]=a0.w;
            a[4]=a1.x; a[5]=a1.y; a[6]=a1.z; a[7]=a1.w;
            b[0]=b0.x; b[1]=b0.y; b[2]=b0.z; b[3]=b0.w;
            b[4]=b1.x; b[5]=b1.y; b[6]=b1.z; b[7]=b1.w;
#pragma unroll
            for (int i = 0; i < 8; i++)
#pragma unroll
                for (int j = 0; j < 8; j++)
                    acc[i][j] = fmaf(a[i], b[j], acc[i][j]);
        }
        __syncthreads();
    }

#pragma unroll
    for (int ih = 0; ih < 2; ih++)
#pragma unroll
    for (int ii = 0; ii < 4; ii++) {
        int m = m0 + ih * 64 + ty * 4 + ii;
#pragma unroll
        for (int jh = 0; jh < 2; jh++) {
            int n = n0 + jh * 64 + tx * 4;
            if (n < Nn) {
                float4 v;
                v.x = acc[ih*4+ii][jh*4+0];
                v.y = acc[ih*4+ii][jh*4+1];
                v.z = acc[ih*4+ii][jh*4+2];
                v.w = acc[ih*4+ii][jh*4+3];
                if (bias) {
                    float4 bb = *(const float4*)(bias + n);
                    v.x += bb.x; v.y += bb.y; v.z += bb.z; v.w += bb.w;
                }
                if (add) {
                    float4 aa = *(const float4*)(add + (size_t)m * ldc + n);
                    v.x += aa.x; v.y += aa.y; v.z += aa.z; v.w += aa.w;
                }
                *(float4*)(Cc + (size_t)m * ldc + n) = v;
            }
        }
    }
}

// ---------------- LayerNorm (optionally gathered input + copy of raw row) ----------------
__global__ __launch_bounds__(128) void ln_kernel(
    const float* __restrict__ in, const int* __restrict__ gidx,
    const float* __restrict__ w, const float* __restrict__ b,
    float* __restrict__ copy_out, float* __restrict__ out)
{
    int row = blockIdx.x;
    int src = gidx ? gidx[row] : row;
    float4 v = *((const float4*)(in + (size_t)src * CD) + threadIdx.x);
    if (copy_out)
        *((float4*)(copy_out + (size_t)row * CD) + threadIdx.x) = v;
    float s  = v.x + v.y + v.z + v.w;
    float ss = v.x*v.x + v.y*v.y + v.z*v.z + v.w*v.w;
#pragma unroll
    for (int o = 16; o; o >>= 1) {
        s  += __shfl_xor_sync(0xffffffffu, s,  o);
        ss += __shfl_xor_sync(0xffffffffu, ss, o);
    }
    __shared__ float sh[10];
    if ((threadIdx.x & 31) == 0) {
        sh[threadIdx.x >> 5] = s;
        sh[4 + (threadIdx.x >> 5)] = ss;
    }
    __syncthreads();
    if (threadIdx.x == 0) {
        float S  = sh[0] + sh[1] + sh[2] + sh[3];
        float SS = sh[4] + sh[5] + sh[6] + sh[7];
        float mu = S * (1.f / CD);
        float var = SS * (1.f / CD) - mu * mu;
        sh[8] = mu;
        sh[9] = rsqrtf(var + 1e-5f);
    }
    __syncthreads();
    float mu = sh[8], r = sh[9];
    float4 wv = *((const float4*)w + threadIdx.x);
    float4 bv = *((const float4*)b + threadIdx.x);
    float4 o;
    o.x = (v.x - mu) * r * wv.x + bv.x;
    o.y = (v.y - mu) * r * wv.y + bv.y;
    o.z = (v.z - mu) * r * wv.z + bv.z;
    o.w = (v.w - mu) * r * wv.w + bv.w;
    *((float4*)(out + (size_t)row * CD) + threadIdx.x) = o;
}

// ---------------- depthwise causal conv1d (k=4) + SiLU ----------------
__global__ void conv_silu_kernel(const float* __restrict__ cw, const float* __restrict__ cb)
{
    int idx = blockIdx.x * blockDim.x + threadIdx.x;   // NPTS*DIN
    int t = idx >> 10, d = idx & 1023;
    float acc = cb[d];
#pragma unroll
    for (int k = 0; k < 4; k++) {
        int tt = t - 3 + k;
        if (tt >= 0) acc = fmaf(g_xz[(size_t)tt * (2*DIN) + d], cw[d * 4 + k], acc);
    }
    float sg = 1.f / (1.f + __expf(-acc));
    g_xc[idx] = acc * sg;
}

__global__ void softplus_kernel()
{
    int i = blockIdx.x * blockDim.x + threadIdx.x;
    float x = g_dt[i];
    g_dt[i] = (x > 0.f) ? (x + log1pf(__expf(-x))) : log1pf(__expf(x));
}

__global__ void aneg_kernel(const float* __restrict__ alog)
{
    int i = blockIdx.x * blockDim.x + threadIdx.x;
    g_An[i] = -__expf(alog[i]);
}

__global__ void gelu_kernel()
{
    int i = blockIdx.x * blockDim.x + threadIdx.x;
    float x = g_g[i];
    g_g[i] = 0.5f * x * (1.f + erff(x * 0.70710678118654752f));
}

// ---------------- scan phase B: per-chunk local scan (h_init = 0) ----------------
__global__ __launch_bounds__(128) void scan_local_kernel()
{
    int d = blockIdx.x * 128 + threadIdx.x;
    int c = blockIdx.y;
    int t0 = c * TCH;
    __shared__ float Bsh[TCH][DST];
    __shared__ float Csh[TCH][DST];
    for (int i = threadIdx.x; i < TCH * DST; i += 128) {
        int t = i >> 4, s = i & 15;
        Bsh[t][s] = g_dbc[(size_t)(t0 + t) * DBCW + 32 + s];
        Csh[t][s] = g_dbc[(size_t)(t0 + t) * DBCW + 48 + s];
    }
    __syncthreads();
    float Av[DST], h[DST];
#pragma unroll
    for (int s = 0; s < DST; s++) { Av[s] = g_An[d * DST + s]; h[s] = 0.f; }
    float dts = 0.f;
    for (int t = 0; t < TCH; t++) {
        float dtv = g_dt[(size_t)(t0 + t) * DIN + d];
        float xv  = g_xc[(size_t)(t0 + t) * DIN + d];
        float dtx = dtv * xv;
        dts += dtv;
        float y = 0.f;
#pragma unroll
        for (int s = 0; s < DST; s++) {
            float a = __expf(dtv * Av[s]);
            h[s] = fmaf(a, h[s], dtx * Bsh[t][s]);
            y = fmaf(h[s], Csh[t][s], y);
        }
        g_y[(size_t)(t0 + t) * DIN + d] = y;
    }
#pragma unroll
    for (int s = 0; s < DST; s++)
        g_Hc[((size_t)c * DIN + d) * DST + s] = h[s];
    g_sd[(size_t)c * DIN + d] = dts;
}

// ---------------- scan phase C: sequential combine over chunk summaries ----------------
__global__ void scan_combine_kernel()
{
    int idx = blockIdx.x * blockDim.x + threadIdx.x;   // DIN*DST
    int d = idx >> 4;
    float Av = g_An[idx];
    float h = 0.f;
    g_hi[idx] = 0.f;                                   // chunk 0 initial state
    for (int c = 1; c < NCH; c++) {
        h = fmaf(__expf(Av * g_sd[(size_t)(c - 1) * DIN + d]), h,
                 g_Hc[(size_t)(c - 1) * DIN * DST + idx]);
        g_hi[(size_t)c * DIN * DST + idx] = h;
    }
}

// ---------------- scan phase D: h_init correction + fused (y + x*D)*silu(z) gate ----------------
__global__ __launch_bounds__(128) void scan_correct_kernel(const float* __restrict__ Dskip)
{
    int d = blockIdx.x * 128 + threadIdx.x;
    int c = blockIdx.y;
    int t0 = c * TCH;
    __shared__ float Csh[TCH][DST];
    for (int i = threadIdx.x; i < TCH * DST; i += 128) {
        int t = i >> 4, s = i & 15;
        Csh[t][s] = g_dbc[(size_t)(t0 + t) * DBCW + 48 + s];
    }
    __syncthreads();
    float Av[DST], hi[DST];
#pragma unroll
    for (int s = 0; s < DST; s++) {
        Av[s] = g_An[d * DST + s];
        hi[s] = g_hi[(size_t)c * DIN * DST + d * DST + s];
    }
    float Dv = Dskip[d];
    float cum = 0.f;
    for (int t = 0; t < TCH; t++) {
        float dtv = g_dt[(size_t)(t0 + t) * DIN + d];
        cum += dtv;
        float corr = 0.f;
#pragma unroll
        for (int s = 0; s < DST; s++)
            corr = fmaf(__expf(Av[s] * cum) * hi[s], Csh[t][s], corr);
        float ysum = g_y[(size_t)(t0 + t) * DIN + d] + corr;
        float xv = g_xc[(size_t)(t0 + t) * DIN + d];
        float zv = g_xz[(size_t)(t0 + t) * (2*DIN) + DIN + d];
        float sg = zv / (1.f + __expf(-zv));
        g_y[(size_t)(t0 + t) * DIN + d] = (ysum + xv * Dv) * sg;
    }
}

// ---------------- final scatter back to original order ----------------
__global__ __launch_bounds__(128) void scatter_kernel(const int* __restrict__ inv, float* __restrict__ out)
{
    int row = blockIdx.x;
    int src = inv[row];
    *((float4*)(out + (size_t)row * CD) + threadIdx.x) =
        *((const float4*)(g_u + (size_t)src * CD) + threadIdx.x);
}

// ---------------- launch ----------------
extern "C" void kernel_launch(void* const* d_in, const int* in_sizes, int n_in,
                              void* d_out, int out_size)
{
    (void)in_sizes; (void)n_in; (void)out_size;
    const float* feat  = (const float*)d_in[0];
    const int*   order = (const int*)  d_in[1];
    const int*   inv   = (const int*)  d_in[2];
    const float* ln1w  = (const float*)d_in[3];
    const float* ln1b  = (const float*)d_in[4];
    const float* inpw  = (const float*)d_in[5];   // (2048, 512)
    const float* convw = (const float*)d_in[6];   // (1024, 4)
    const float* convb = (const float*)d_in[7];
    const float* xpw   = (const float*)d_in[8];   // (64, 1024)
    const float* dtw   = (const float*)d_in[9];   // (1024, 32)
    const float* dtb   = (const float*)d_in[10];
    const float* alog  = (const float*)d_in[11];  // (1024, 16)
    const float* dskip = (const float*)d_in[12];
    const float* outw  = (const float*)d_in[13];  // (512, 1024)
    const float* ln2w  = (const float*)d_in[14];
    const float* ln2b  = (const float*)d_in[15];
    const float* fw1   = (const float*)d_in[16];  // (512, 1024)
    const float* fb1   = (const float*)d_in[17];
    const float* fw2   = (const float*)d_in[18];  // (1024, 512)
    const float* fb2   = (const float*)d_in[19];
    float* out = (float*)d_out;

    void *pf, *pu, *pxz, *pxc, *pdbc, *pdt, *py, *px1, *ph2, *pg;
    cudaGetSymbolAddress(&pf,  g_f);
    cudaGetSymbolAddress(&pu,  g_u);
    cudaGetSymbolAddress(&pxz, g_xz);
    cudaGetSymbolAddress(&pxc, g_xc);
    cudaGetSymbolAddress(&pdbc,g_dbc);
    cudaGetSymbolAddress(&pdt, g_dt);
    cudaGetSymbolAddress(&py,  g_y);
    cudaGetSymbolAddress(&px1, g_x1);
    cudaGetSymbolAddress(&ph2, g_h2);
    cudaGetSymbolAddress(&pg,  g_g);

    // 1) gather + LN1 (stores raw gathered f and normalized u)
    ln_kernel<<<NPTS, 128>>>(feat, order, ln1w, ln1b, (float*)pf, (float*)pu);

    // 2) xz = u @ in_proj_w^T   (16384 x 2048 x 512)
    sgemm<true><<<dim3(16, 128), 256>>>((const float*)pu, CD, inpw, CD,
                                        nullptr, nullptr, (float*)pxz, 2*DIN,
                                        NPTS, 2*DIN, CD);

    // 3) depthwise causal conv + SiLU -> xc
    conv_silu_kernel<<<(NPTS*DIN)/256, 256>>>(convw, convb);

    // 4) dbc = xc @ x_proj_w^T   (16384 x 64 x 1024)
    sgemm<true><<<dim3(1, 128), 256>>>((const float*)pxc, DIN, xpw, DIN,
                                       nullptr, nullptr, (float*)pdbc, DBCW,
                                       NPTS, DBCW, DIN);

    // 5) dt_raw = dbc[:, :32] @ dt_proj_w^T + b, then softplus
    sgemm<true><<<dim3(8, 128), 256>>>((const float*)pdbc, DBCW, dtw, 32,
                                       dtb, nullptr, (float*)pdt, DIN,
                                       NPTS, DIN, 32);
    softplus_kernel<<<(NPTS*DIN)/256, 256>>>();

    // 6) A = -exp(A_log)
    aneg_kernel<<<(DIN*DST)/256, 256>>>(alog);

    // 7) chunked selective scan: local -> combine -> correct(+gate)
    scan_local_kernel<<<dim3(DIN/128, NCH), 128>>>();
    scan_combine_kernel<<<(DIN*DST)/256, 256>>>();
    scan_correct_kernel<<<dim3(DIN/128, NCH), 128>>>(dskip);

    // 8) x1 = f + y @ out_proj_w^T   (16384 x 512 x 1024, fused residual)
    sgemm<true><<<dim3(4, 128), 256>>>((const float*)py, DIN, outw, DIN,
                                       nullptr, (const float*)pf, (float*)px1, CD,
                                       NPTS, CD, DIN);

    // 9) h2 = LN2(x1)
    ln_kernel<<<NPTS, 128>>>((const float*)px1, nullptr, ln2w, ln2b,
                             nullptr, (float*)ph2);

    // 10) g = h2 @ ffn_w1 + b1, GeLU   (16384 x 1024 x 512)
    sgemm<false><<<dim3(8, 128), 256>>>((const float*)ph2, CD, fw1, MLPD,
                                        fb1, nullptr, (float*)pg, MLPD,
                                        NPTS, MLPD, CD);
    gelu_kernel<<<(NPTS*MLPD)/256, 256>>>();

    // 11) x2 = x1 + g @ ffn_w2 + b2   (16384 x 512 x 1024, fused residual) -> g_u
    sgemm<false><<<dim3(4, 128), 256>>>((const float*)pg, MLPD, fw2, CD,
                                        fb2, (const float*)px1, (float*)pu, CD,
                                        NPTS, CD, MLPD);

    // 12) out[i] = x2[inverse[i]]
    scatter_kernel<<<NPTS, 128>>>(inv, out);
}